// round 2
// baseline (speedup 1.0000x reference)
#include <cuda_runtime.h>
#include <cstdint>

#define VOCAB 100000
#define EMBED 64
#define BATCH 1024
#define SEQ   50
#define KIDS  20
#define NPOS  (BATCH * SEQ)   // 51200

// Scratch: transposed weights WT[v][e], 25.6 MB (fits in L2).
__device__ float g_WT[(size_t)VOCAB * EMBED];

// ---------------------------------------------------------------------------
// Kernel 1: transpose W[E,V] -> WT[V,E] via shared-memory tiles.
// Block handles a 32-wide slab of v across all 64 e's.
// ---------------------------------------------------------------------------
__global__ __launch_bounds__(256) void transpose_kernel(const float* __restrict__ W,
                                                        float* __restrict__ WT) {
    __shared__ float s[EMBED][33];  // [e][v_local], pad to kill bank conflicts
    const int v0 = blockIdx.x * 32;
    const int tx = threadIdx.x;     // 0..31 (along v)
    const int ty = threadIdx.y;     // 0..7  (along e)

    // Load: coalesced along v for each e row.
    #pragma unroll
    for (int e = ty; e < EMBED; e += 8) {
        int v = v0 + tx;
        s[e][tx] = (v < VOCAB) ? W[(size_t)e * VOCAB + v] : 0.0f;
    }
    __syncthreads();

    // Store: coalesced along e for each v.
    const int lin = ty * 32 + tx;        // 0..255
    const int e   = lin & 63;            // 0..63
    const int vi0 = lin >> 6;            // 0..3
    #pragma unroll
    for (int vi = vi0; vi < 32; vi += 4) {
        int v = v0 + vi;
        if (v < VOCAB) WT[(size_t)v * EMBED + e] = s[e][vi];
    }
}

// ---------------------------------------------------------------------------
// Kernel 2: one warp per (b,s) position. Each lane owns a float2 slice of the
// 64-wide embedding. 20 fully-coalesced 256B row reads from L2-resident WT.
// ---------------------------------------------------------------------------
__global__ __launch_bounds__(256) void gather_kernel(const int* __restrict__ ids,
                                                     const float* __restrict__ WT,
                                                     const float* __restrict__ bias,
                                                     float* __restrict__ out) {
    const int gwarp = (blockIdx.x * blockDim.x + threadIdx.x) >> 5;
    const int lane  = threadIdx.x & 31;
    if (gwarp >= NPOS) return;

    // Lanes 0..19 each fetch one id; broadcast via shuffle inside the loop.
    const int* idp = ids + (size_t)gwarp * KIDS;
    int myid = (lane < KIDS) ? idp[lane] : 0;

    float2 acc = make_float2(0.0f, 0.0f);
    #pragma unroll
    for (int k = 0; k < KIDS; ++k) {
        int id = __shfl_sync(0xffffffffu, myid, k);
        float2 v = reinterpret_cast<const float2*>(WT + (size_t)id * EMBED)[lane];
        acc.x += v.x;
        acc.y += v.y;
    }

    float2 bb = reinterpret_cast<const float2*>(bias)[lane];
    reinterpret_cast<float2*>(out + (size_t)gwarp * EMBED)[lane] =
        make_float2(acc.x + bb.x, acc.y + bb.y);
}

extern "C" void kernel_launch(void* const* d_in, const int* in_sizes, int n_in,
                              void* d_out, int out_size) {
    const int*   ids  = (const int*)d_in[0];    // [B,S,K] int32
    const float* W    = (const float*)d_in[1];  // [E,V] float32
    const float* bias = (const float*)d_in[2];  // [E]   float32
    float*       out  = (float*)d_out;          // [B,S,E] float32

    float* WT = nullptr;
    cudaGetSymbolAddress((void**)&WT, g_WT);

    // 1) Transpose W into L2-friendly [V, E] layout.
    dim3 tb(32, 8);
    int tgrid = (VOCAB + 31) / 32;
    transpose_kernel<<<tgrid, tb>>>(W, WT);

    // 2) Gather-sum: 51200 warps, 8 warps/block.
    int threads = 256;
    int blocks  = (NPOS * 32 + threads - 1) / threads;
    gather_kernel<<<blocks, threads>>>(ids, WT, bias, out);
}

// round 5
// speedup vs baseline: 1.0655x; 1.0655x over previous
#include <cuda_runtime.h>
#include <cstdint>

#define VOCAB 100000
#define EMBED 64
#define BATCH 1024
#define SEQ   50
#define KIDS  20
#define NPOS  (BATCH * SEQ)   // 51200

// Scratch: transposed weights WT[v][e], 25.6 MB (L2-resident at 126 MB L2).
__device__ float g_WT[(size_t)VOCAB * EMBED];

// ---------------------------------------------------------------------------
// Kernel 1: transpose W[E,V] -> WT[V,E]. 64e x 64v tiles, float4 on both
// global sides. Shared stride 65 keeps conflicts to <=2-way (not binding).
// ---------------------------------------------------------------------------
__global__ __launch_bounds__(256) void transpose_kernel(const float* __restrict__ W,
                                                        float* __restrict__ WT) {
    __shared__ float s[64 * 65];
    const int v0 = blockIdx.x * 64;
    const int t  = threadIdx.x;

    // Load phase: 1024 float4 (along v), 4 per thread, coalesced per e-row.
    #pragma unroll
    for (int r = 0; r < 4; ++r) {
        int f = t + r * 256;         // 0..1023
        int e = f >> 4;              // 0..63
        int c = f & 15;              // float4 col within tile
        int v = v0 + c * 4;
        float4 val;
        if (v + 3 < VOCAB) {
            val = *reinterpret_cast<const float4*>(W + (size_t)e * VOCAB + v);
        } else {
            float tmp[4];
            #pragma unroll
            for (int j = 0; j < 4; ++j)
                tmp[j] = (v + j < VOCAB) ? W[(size_t)e * VOCAB + v + j] : 0.0f;
            val = make_float4(tmp[0], tmp[1], tmp[2], tmp[3]);
        }
        int base = e * 65 + c * 4;
        s[base + 0] = val.x; s[base + 1] = val.y;
        s[base + 2] = val.z; s[base + 3] = val.w;
    }
    __syncthreads();

    // Store phase: each thread writes float4 along e; half-warp covers one
    // 256B v-row -> fully coalesced STG.128.
    const int f4  = t & 15;          // float4 index along e
    const int vl0 = t >> 4;          // 0..15
    #pragma unroll
    for (int g = 0; g < 4; ++g) {
        int vl = vl0 + g * 16;
        int v  = v0 + vl;
        if (v < VOCAB) {
            int e = f4 * 4;
            float4 o;
            o.x = s[(e + 0) * 65 + vl];
            o.y = s[(e + 1) * 65 + vl];
            o.z = s[(e + 2) * 65 + vl];
            o.w = s[(e + 3) * 65 + vl];
            *reinterpret_cast<float4*>(WT + (size_t)v * EMBED + e) = o;
        }
    }
}

// ---------------------------------------------------------------------------
// Kernel 2: gather-sum. One warp = 2 positions; each half-warp owns a 256B
// WT row as 16 x float4. Ids staged through shared memory (coalesced load,
// broadcast LDS per iteration). 20 independent LDG.128 per thread -> MLP=20.
// ---------------------------------------------------------------------------
__global__ __launch_bounds__(256) void gather_kernel(const int* __restrict__ ids,
                                                     const float* __restrict__ WT,
                                                     const float* __restrict__ bias,
                                                     float* __restrict__ out) {
    __shared__ int sid[16 * KIDS];   // 16 positions per block x 20 ids = 320
    const int posBase = blockIdx.x * 16;
    const int t = threadIdx.x;

    // FIX: 320 ids with 256 threads — strided load covers all of sid[].
    #pragma unroll
    for (int i = t; i < 16 * KIDS; i += 256)
        sid[i] = ids[(size_t)posBase * KIDS + i];
    __syncthreads();

    const int warp  = t >> 5;        // 0..7
    const int half  = (t >> 4) & 1;  // 0/1
    const int lane4 = t & 15;        // float4 slice of the 64-wide embedding
    const int pos   = warp * 2 + half;

    const int* myids = sid + pos * KIDS;

    float4 acc = make_float4(0.0f, 0.0f, 0.0f, 0.0f);
    #pragma unroll
    for (int k = 0; k < KIDS; ++k) {
        int id = myids[k];
        float4 v = reinterpret_cast<const float4*>(WT + (size_t)id * EMBED)[lane4];
        acc.x += v.x; acc.y += v.y; acc.z += v.z; acc.w += v.w;
    }

    float4 bb = reinterpret_cast<const float4*>(bias)[lane4];
    acc.x += bb.x; acc.y += bb.y; acc.z += bb.z; acc.w += bb.w;

    reinterpret_cast<float4*>(out + (size_t)(posBase + pos) * EMBED)[lane4] = acc;
}

extern "C" void kernel_launch(void* const* d_in, const int* in_sizes, int n_in,
                              void* d_out, int out_size) {
    const int*   ids  = (const int*)d_in[0];    // [B,S,K] int32
    const float* W    = (const float*)d_in[1];  // [E,V] float32
    const float* bias = (const float*)d_in[2];  // [E]   float32
    float*       out  = (float*)d_out;          // [B,S,E] float32

    float* WT = nullptr;
    cudaGetSymbolAddress((void**)&WT, g_WT);

    // 1) Transpose W into [V, E] layout (L2-resident, coalesced rows).
    int tgrid = (VOCAB + 63) / 64;              // 1563
    transpose_kernel<<<tgrid, 256>>>(W, WT);

    // 2) Gather-sum: 16 positions per 256-thread block.
    gather_kernel<<<NPOS / 16, 256>>>(ids, WT, bias, out);
}